// round 6
// baseline (speedup 1.0000x reference)
#include <cuda_runtime.h>
#include <math.h>
#include <stdint.h>

#define BB 8
#define SS 2048
#define DD 768
#define HH 12
#define HD 64

// Scratch (static device globals — allocation-free per harness rules)
__device__ float g_Q[BB*HH*SS*HD];
__device__ float g_K[BB*HH*SS*HD];
__device__ float g_V[BB*HH*SS*HD];
__device__ float g_ctx[BB*SS*DD];

__device__ __forceinline__ uint32_t f2tf(float x) {
    uint32_t r;
    asm("cvt.rna.tf32.f32 %0, %1;" : "=r"(r) : "f"(x));
    return r;
}

__device__ __forceinline__ void mma8(float* c, const uint32_t* a, const uint32_t* b) {
    asm volatile(
        "mma.sync.aligned.m16n8k8.row.col.f32.tf32.tf32.f32 "
        "{%0,%1,%2,%3},{%4,%5,%6,%7},{%8,%9},{%0,%1,%2,%3};\n"
        : "+f"(c[0]), "+f"(c[1]), "+f"(c[2]), "+f"(c[3])
        : "r"(a[0]), "r"(a[1]), "r"(a[2]), "r"(a[3]), "r"(b[0]), "r"(b[1]));
}

// ---------------------------------------------------------------------------
// Kernel 1: per-head QKV projection (tf32 tensor core).
// grid = (S/128, B*H, 3), block = 256 (8 warps, 4x2; warp tile 32x32).
// C[128x64] = x[b, s0:s0+128, :] @ W[h][768x64] + bias[h]
// ---------------------------------------------------------------------------
__global__ void __launch_bounds__(256) qkv_kernel(
    const float* __restrict__ x,
    const float* __restrict__ Wq, const float* __restrict__ bq,
    const float* __restrict__ Wk, const float* __restrict__ bk,
    const float* __restrict__ Wv, const float* __restrict__ bv)
{
    __shared__ uint32_t As[128 * 36];  // m-major, stride 36 (=4 mod 32)
    __shared__ uint32_t Bs[32 * 72];   // k-major, stride 72 (=8 mod 32)

    int tid = threadIdx.x;
    int wid = tid >> 5, lane = tid & 31;
    int g = lane >> 2, t = lane & 3;
    int wm = wid & 3, wn = wid >> 2;
    int s0 = blockIdx.x * 128;
    int bh = blockIdx.y;
    int b = bh / HH, h = bh % HH;

    const float* W; const float* bias; float* outp;
    if (blockIdx.z == 0)      { W = Wq; bias = bq; outp = g_Q; }
    else if (blockIdx.z == 1) { W = Wk; bias = bk; outp = g_K; }
    else                      { W = Wv; bias = bv; outp = g_V; }
    W += h * DD * HD;
    bias += h * HD;

    const float* A = x + ((long)b * SS + s0) * DD;

    float c[2][4][4];
    #pragma unroll
    for (int s_ = 0; s_ < 2; s_++)
        #pragma unroll
        for (int nt = 0; nt < 4; nt++)
            #pragma unroll
            for (int j = 0; j < 4; j++) c[s_][nt][j] = 0.f;

    for (int k0 = 0; k0 < DD; k0 += 32) {
        // A tile: 128 rows x 32 cols (8 float4 segs per row)
        #pragma unroll
        for (int i = 0; i < 4; i++) {
            int idx = tid + i * 256;
            int r = idx >> 3, sg = idx & 7;
            float4 v = *(const float4*)(A + (long)r * DD + k0 + sg * 4);
            uint4 u = make_uint4(f2tf(v.x), f2tf(v.y), f2tf(v.z), f2tf(v.w));
            *(uint4*)(As + r * 36 + sg * 4) = u;
        }
        // B tile: 32 rows (k) x 64 cols
        #pragma unroll
        for (int i = 0; i < 2; i++) {
            int idx = tid + i * 256;
            int r = idx >> 4, sg = idx & 15;
            float4 v = *(const float4*)(W + (long)(k0 + r) * HD + sg * 4);
            uint4 u = make_uint4(f2tf(v.x), f2tf(v.y), f2tf(v.z), f2tf(v.w));
            *(uint4*)(Bs + r * 72 + sg * 4) = u;
        }
        __syncthreads();

        #pragma unroll
        for (int kk = 0; kk < 32; kk += 8) {
            uint32_t a[2][4], bf[4][2];
            #pragma unroll
            for (int s_ = 0; s_ < 2; s_++) {
                int row = wm * 32 + s_ * 16 + g;
                a[s_][0] = As[row * 36 + kk + t];
                a[s_][1] = As[(row + 8) * 36 + kk + t];
                a[s_][2] = As[row * 36 + kk + t + 4];
                a[s_][3] = As[(row + 8) * 36 + kk + t + 4];
            }
            #pragma unroll
            for (int nt = 0; nt < 4; nt++) {
                int col = wn * 32 + nt * 8 + g;
                bf[nt][0] = Bs[(kk + t) * 72 + col];
                bf[nt][1] = Bs[(kk + t + 4) * 72 + col];
            }
            #pragma unroll
            for (int s_ = 0; s_ < 2; s_++)
                #pragma unroll
                for (int nt = 0; nt < 4; nt++)
                    mma8(c[s_][nt], a[s_], bf[nt]);
        }
        __syncthreads();
    }

    #pragma unroll
    for (int s_ = 0; s_ < 2; s_++) {
        int row = s0 + wm * 32 + s_ * 16 + g;
        #pragma unroll
        for (int nt = 0; nt < 4; nt++) {
            int col = wn * 32 + nt * 8 + 2 * t;
            float b0 = bias[col], b1 = bias[col + 1];
            long base0 = ((long)bh * SS + row) * HD + col;
            long base1 = ((long)bh * SS + row + 8) * HD + col;
            outp[base0]     = c[s_][nt][0] + b0;
            outp[base0 + 1] = c[s_][nt][1] + b1;
            outp[base1]     = c[s_][nt][2] + b0;
            outp[base1 + 1] = c[s_][nt][3] + b1;
        }
    }
}

// ---------------------------------------------------------------------------
// Kernel 2: flash attention (tf32 tensor core).
// grid = (S/128, B*H), block = 256 (8 warps; each warp owns 16 q-rows).
// dynamic smem = (128*68 + 64*68 + 64*72 + 128*68) * 4 bytes = 105472.
// ---------------------------------------------------------------------------
#define ATTN_SMEM ((128*68 + 64*68 + 64*72 + 128*68) * 4)

__global__ void __launch_bounds__(256) attn_kernel()
{
    extern __shared__ uint32_t sm[];
    uint32_t* Qs = sm;                       // [128][68]
    uint32_t* Ks = Qs + 128 * 68;            // [64][68]
    uint32_t* Vs = Ks + 64 * 68;             // [64][72]  (stride 72: =8 mod 32)
    uint32_t* Ps = Vs + 64 * 72;             // [128][68]

    int tid = threadIdx.x;
    int wid = tid >> 5, lane = tid & 31;
    int g = lane >> 2, t = lane & 3;
    int m0 = wid * 16;
    int q0 = blockIdx.x * 128;
    int bh = blockIdx.y;

    const float* Qg = g_Q + ((long)bh * SS + q0) * HD;
    const float* Kg = g_K + (long)bh * SS * HD;
    const float* Vg = g_V + (long)bh * SS * HD;

    // Load Q tile: 128 x 64
    #pragma unroll
    for (int i = 0; i < 8; i++) {
        int idx = tid + i * 256;
        int r = idx >> 4, sg = idx & 15;
        float4 v = *(const float4*)(Qg + (long)r * HD + sg * 4);
        uint4 u = make_uint4(f2tf(v.x), f2tf(v.y), f2tf(v.z), f2tf(v.w));
        *(uint4*)(Qs + r * 68 + sg * 4) = u;
    }

    float o[8][4];
    #pragma unroll
    for (int nt = 0; nt < 8; nt++)
        #pragma unroll
        for (int j = 0; j < 4; j++) o[nt][j] = 0.f;
    float mrow0 = -1e30f, mrow1 = -1e30f;
    float lrow0 = 0.f, lrow1 = 0.f;
    const float inv_scale = 1.0f / (8.0f + 1e-6f);  // 1/(sqrt(64)+EPS)

    for (int kt = 0; kt < SS; kt += 64) {
        __syncthreads();  // previous iteration done with Ks/Vs
        #pragma unroll
        for (int i = 0; i < 4; i++) {
            int idx = tid + i * 256;
            int r = idx >> 4, sg = idx & 15;
            float4 v = *(const float4*)(Kg + (long)(kt + r) * HD + sg * 4);
            *(uint4*)(Ks + r * 68 + sg * 4) =
                make_uint4(f2tf(v.x), f2tf(v.y), f2tf(v.z), f2tf(v.w));
            float4 w = *(const float4*)(Vg + (long)(kt + r) * HD + sg * 4);
            *(uint4*)(Vs + r * 72 + sg * 4) =
                make_uint4(f2tf(w.x), f2tf(w.y), f2tf(w.z), f2tf(w.w));
        }
        __syncthreads();

        // Phase 1: S = Q @ K^T  (warp: 16 rows x 64 keys)
        float s[8][4];
        #pragma unroll
        for (int nt = 0; nt < 8; nt++)
            #pragma unroll
            for (int j = 0; j < 4; j++) s[nt][j] = 0.f;

        #pragma unroll
        for (int kk = 0; kk < 64; kk += 8) {
            uint32_t a[4];
            a[0] = Qs[(m0 + g) * 68 + kk + t];
            a[1] = Qs[(m0 + g + 8) * 68 + kk + t];
            a[2] = Qs[(m0 + g) * 68 + kk + t + 4];
            a[3] = Qs[(m0 + g + 8) * 68 + kk + t + 4];
            #pragma unroll
            for (int nt = 0; nt < 8; nt++) {
                uint32_t bf[2];
                bf[0] = Ks[(nt * 8 + g) * 68 + kk + t];
                bf[1] = Ks[(nt * 8 + g) * 68 + kk + t + 4];
                mma8(s[nt], a, bf);
            }
        }

        // Online softmax (rows g and g+8 of this warp's 16-row tile)
        #pragma unroll
        for (int nt = 0; nt < 8; nt++)
            #pragma unroll
            for (int j = 0; j < 4; j++) s[nt][j] *= inv_scale;

        float mx0 = -1e30f, mx1 = -1e30f;
        #pragma unroll
        for (int nt = 0; nt < 8; nt++) {
            mx0 = fmaxf(mx0, fmaxf(s[nt][0], s[nt][1]));
            mx1 = fmaxf(mx1, fmaxf(s[nt][2], s[nt][3]));
        }
        mx0 = fmaxf(mx0, __shfl_xor_sync(0xffffffffu, mx0, 1));
        mx0 = fmaxf(mx0, __shfl_xor_sync(0xffffffffu, mx0, 2));
        mx1 = fmaxf(mx1, __shfl_xor_sync(0xffffffffu, mx1, 1));
        mx1 = fmaxf(mx1, __shfl_xor_sync(0xffffffffu, mx1, 2));

        float mn0 = fmaxf(mrow0, mx0), mn1 = fmaxf(mrow1, mx1);
        float cr0 = __expf(mrow0 - mn0), cr1 = __expf(mrow1 - mn1);
        float rs0 = 0.f, rs1 = 0.f;
        #pragma unroll
        for (int nt = 0; nt < 8; nt++) {
            s[nt][0] = __expf(s[nt][0] - mn0);
            s[nt][1] = __expf(s[nt][1] - mn0);
            s[nt][2] = __expf(s[nt][2] - mn1);
            s[nt][3] = __expf(s[nt][3] - mn1);
            rs0 += s[nt][0] + s[nt][1];
            rs1 += s[nt][2] + s[nt][3];
        }
        rs0 += __shfl_xor_sync(0xffffffffu, rs0, 1);
        rs0 += __shfl_xor_sync(0xffffffffu, rs0, 2);
        rs1 += __shfl_xor_sync(0xffffffffu, rs1, 1);
        rs1 += __shfl_xor_sync(0xffffffffu, rs1, 2);
        lrow0 = lrow0 * cr0 + rs0;
        lrow1 = lrow1 * cr1 + rs1;
        mrow0 = mn0; mrow1 = mn1;

        #pragma unroll
        for (int nt = 0; nt < 8; nt++) {
            o[nt][0] *= cr0; o[nt][1] *= cr0;
            o[nt][2] *= cr1; o[nt][3] *= cr1;
            int col = nt * 8 + 2 * t;
            Ps[(m0 + g) * 68 + col]         = f2tf(s[nt][0]);
            Ps[(m0 + g) * 68 + col + 1]     = f2tf(s[nt][1]);
            Ps[(m0 + g + 8) * 68 + col]     = f2tf(s[nt][2]);
            Ps[(m0 + g + 8) * 68 + col + 1] = f2tf(s[nt][3]);
        }
        __syncwarp();  // warp-private P rows: warp-level visibility suffices

        // Phase 2: O += P @ V
        #pragma unroll
        for (int kk = 0; kk < 64; kk += 8) {
            uint32_t a[4];
            a[0] = Ps[(m0 + g) * 68 + kk + t];
            a[1] = Ps[(m0 + g + 8) * 68 + kk + t];
            a[2] = Ps[(m0 + g) * 68 + kk + t + 4];
            a[3] = Ps[(m0 + g + 8) * 68 + kk + t + 4];
            #pragma unroll
            for (int nt = 0; nt < 8; nt++) {
                uint32_t bf[2];
                bf[0] = Vs[(kk + t) * 72 + nt * 8 + g];
                bf[1] = Vs[(kk + t + 4) * 72 + nt * 8 + g];
                mma8(o[nt], a, bf);
            }
        }
    }

    // Epilogue: normalize, write ctx in [B, S, H*HD] head-concat layout
    int b = bh / HH, h = bh % HH;
    float il0 = 1.0f / lrow0, il1 = 1.0f / lrow1;
    long r0 = ((long)b * SS + q0 + m0 + g) * DD + h * HD;
    long r1 = ((long)b * SS + q0 + m0 + g + 8) * DD + h * HD;
    #pragma unroll
    for (int nt = 0; nt < 8; nt++) {
        int col = nt * 8 + 2 * t;
        g_ctx[r0 + col]     = o[nt][0] * il0;
        g_ctx[r0 + col + 1] = o[nt][1] * il0;
        g_ctx[r1 + col]     = o[nt][2] * il1;
        g_ctx[r1 + col + 1] = o[nt][3] * il1;
    }
}

// ---------------------------------------------------------------------------
// Kernel 3: output projection (tf32). [B*S,768] @ [768,768] + bias -> d_out.
// grid = (B*S/128, D/64), block = 256 (warp tile 32x32).
// ---------------------------------------------------------------------------
__global__ void __launch_bounds__(256) proj_kernel(
    const float* __restrict__ Wp, const float* __restrict__ bp,
    float* __restrict__ out)
{
    __shared__ uint32_t As[128 * 36];
    __shared__ uint32_t Bs[32 * 72];

    int tid = threadIdx.x;
    int wid = tid >> 5, lane = tid & 31;
    int g = lane >> 2, t = lane & 3;
    int wm = wid & 3, wn = wid >> 2;
    int m0 = blockIdx.x * 128;
    int n0 = blockIdx.y * 64;

    const float* A = g_ctx + (long)m0 * DD;

    float c[2][4][4];
    #pragma unroll
    for (int s_ = 0; s_ < 2; s_++)
        #pragma unroll
        for (int nt = 0; nt < 4; nt++)
            #pragma unroll
            for (int j = 0; j < 4; j++) c[s_][nt][j] = 0.f;

    for (int k0 = 0; k0 < DD; k0 += 32) {
        #pragma unroll
        for (int i = 0; i < 4; i++) {
            int idx = tid + i * 256;
            int r = idx >> 3, sg = idx & 7;
            float4 v = *(const float4*)(A + (long)r * DD + k0 + sg * 4);
            *(uint4*)(As + r * 36 + sg * 4) =
                make_uint4(f2tf(v.x), f2tf(v.y), f2tf(v.z), f2tf(v.w));
        }
        #pragma unroll
        for (int i = 0; i < 2; i++) {
            int idx = tid + i * 256;
            int r = idx >> 4, sg = idx & 15;
            float4 v = *(const float4*)(Wp + (long)(k0 + r) * DD + n0 + sg * 4);
            *(uint4*)(Bs + r * 72 + sg * 4) =
                make_uint4(f2tf(v.x), f2tf(v.y), f2tf(v.z), f2tf(v.w));
        }
        __syncthreads();

        #pragma unroll
        for (int kk = 0; kk < 32; kk += 8) {
            uint32_t a[2][4], bf[4][2];
            #pragma unroll
            for (int s_ = 0; s_ < 2; s_++) {
                int row = wm * 32 + s_ * 16 + g;
                a[s_][0] = As[row * 36 + kk + t];
                a[s_][1] = As[(row + 8) * 36 + kk + t];
                a[s_][2] = As[row * 36 + kk + t + 4];
                a[s_][3] = As[(row + 8) * 36 + kk + t + 4];
            }
            #pragma unroll
            for (int nt = 0; nt < 4; nt++) {
                int col = wn * 32 + nt * 8 + g;
                bf[nt][0] = Bs[(kk + t) * 72 + col];
                bf[nt][1] = Bs[(kk + t + 4) * 72 + col];
            }
            #pragma unroll
            for (int s_ = 0; s_ < 2; s_++)
                #pragma unroll
                for (int nt = 0; nt < 4; nt++)
                    mma8(c[s_][nt], a[s_], bf[nt]);
        }
        __syncthreads();
    }

    #pragma unroll
    for (int s_ = 0; s_ < 2; s_++) {
        int row = m0 + wm * 32 + s_ * 16 + g;
        #pragma unroll
        for (int nt = 0; nt < 4; nt++) {
            int col = n0 + wn * 32 + nt * 8 + 2 * t;
            float b0 = bp[col], b1 = bp[col + 1];
            out[(long)row * DD + col]           = c[s_][nt][0] + b0;
            out[(long)row * DD + col + 1]       = c[s_][nt][1] + b1;
            out[(long)(row + 8) * DD + col]     = c[s_][nt][2] + b0;
            out[(long)(row + 8) * DD + col + 1] = c[s_][nt][3] + b1;
        }
    }
}

// ---------------------------------------------------------------------------
extern "C" void kernel_launch(void* const* d_in, const int* in_sizes, int n_in,
                              void* d_out, int out_size)
{
    const float* x  = (const float*)d_in[0];
    const float* Wq = (const float*)d_in[1];
    const float* bq = (const float*)d_in[2];
    const float* Wk = (const float*)d_in[3];
    const float* bk = (const float*)d_in[4];
    const float* Wv = (const float*)d_in[5];
    const float* bv = (const float*)d_in[6];
    const float* Wp = (const float*)d_in[7];
    const float* bp = (const float*)d_in[8];
    float* out = (float*)d_out;

    cudaFuncSetAttribute(attn_kernel, cudaFuncAttributeMaxDynamicSharedMemorySize,
                         ATTN_SMEM);

    qkv_kernel<<<dim3(SS / 128, BB * HH, 3), 256>>>(x, Wq, bq, Wk, bk, Wv, bv);
    attn_kernel<<<dim3(SS / 128, BB * HH), 256, ATTN_SMEM>>>();
    proj_kernel<<<dim3((BB * SS) / 128, DD / 64), 256>>>(Wp, bp, out);
}

// round 7
// speedup vs baseline: 1.0012x; 1.0012x over previous
#include <cuda_runtime.h>
#include <math.h>
#include <stdint.h>

#define BB 8
#define SS 2048
#define DD 768
#define HH 12
#define HD 64

__device__ float g_Q[BB*HH*SS*HD];
__device__ float g_K[BB*HH*SS*HD];
__device__ float g_V[BB*HH*SS*HD];
__device__ float g_ctx[BB*SS*DD];

__device__ __forceinline__ uint32_t f2tf(float x) {
    uint32_t r;
    asm("cvt.rna.tf32.f32 %0, %1;" : "=r"(r) : "f"(x));
    return r;
}

__device__ __forceinline__ void mma8(float* c, const uint32_t* a, const uint32_t* b) {
    asm volatile(
        "mma.sync.aligned.m16n8k8.row.col.f32.tf32.tf32.f32 "
        "{%0,%1,%2,%3},{%4,%5,%6,%7},{%8,%9},{%0,%1,%2,%3};\n"
        : "+f"(c[0]), "+f"(c[1]), "+f"(c[2]), "+f"(c[3])
        : "r"(a[0]), "r"(a[1]), "r"(a[2]), "r"(a[3]), "r"(b[0]), "r"(b[1]));
}

__device__ __forceinline__ uint4 tf4(float4 v) {
    return make_uint4(f2tf(v.x), f2tf(v.y), f2tf(v.z), f2tf(v.w));
}

// ---------------------------------------------------------------------------
// Kernel 1: QKV projection, software-pipelined (prefetch next tile into regs
// before the MMA phase so LDG latency hides behind tensor work).
// grid = (S/128, B*H, 3), block = 256.
// ---------------------------------------------------------------------------
__global__ void __launch_bounds__(256) qkv_kernel(
    const float* __restrict__ x,
    const float* __restrict__ Wq, const float* __restrict__ bq,
    const float* __restrict__ Wk, const float* __restrict__ bk,
    const float* __restrict__ Wv, const float* __restrict__ bv)
{
    __shared__ uint32_t As[128 * 36];
    __shared__ uint32_t Bs[32 * 72];

    int tid = threadIdx.x;
    int wid = tid >> 5, lane = tid & 31;
    int g = lane >> 2, t = lane & 3;
    int wm = wid & 3, wn = wid >> 2;
    int s0 = blockIdx.x * 128;
    int bh = blockIdx.y;
    int b = bh / HH, h = bh % HH;

    const float* W; const float* bias; float* outp;
    if (blockIdx.z == 0)      { W = Wq; bias = bq; outp = g_Q; }
    else if (blockIdx.z == 1) { W = Wk; bias = bk; outp = g_K; }
    else                      { W = Wv; bias = bv; outp = g_V; }
    W += h * DD * HD;
    bias += h * HD;

    const float* A = x + ((long)b * SS + s0) * DD;

    // Per-thread staging coordinates
    int ar[4], asg[4], br[2], bsg[2];
    #pragma unroll
    for (int i = 0; i < 4; i++) { int idx = tid + i*256; ar[i] = idx >> 3; asg[i] = idx & 7; }
    #pragma unroll
    for (int i = 0; i < 2; i++) { int idx = tid + i*256; br[i] = idx >> 4; bsg[i] = idx & 15; }

    float c[2][4][4];
    #pragma unroll
    for (int s_ = 0; s_ < 2; s_++)
        #pragma unroll
        for (int nt = 0; nt < 4; nt++)
            #pragma unroll
            for (int j = 0; j < 4; j++) c[s_][nt][j] = 0.f;

    // Prologue: load tile k0=0 into registers
    float4 aR[4], bR[2];
    #pragma unroll
    for (int i = 0; i < 4; i++)
        aR[i] = *(const float4*)(A + (long)ar[i] * DD + asg[i] * 4);
    #pragma unroll
    for (int i = 0; i < 2; i++)
        bR[i] = *(const float4*)(W + (long)br[i] * HD + bsg[i] * 4);

    for (int k0 = 0; k0 < DD; k0 += 32) {
        // Commit current tile to smem (with RNA tf32 convert)
        #pragma unroll
        for (int i = 0; i < 4; i++)
            *(uint4*)(As + ar[i] * 36 + asg[i] * 4) = tf4(aR[i]);
        #pragma unroll
        for (int i = 0; i < 2; i++)
            *(uint4*)(Bs + br[i] * 72 + bsg[i] * 4) = tf4(bR[i]);
        __syncthreads();

        // Prefetch next tile (overlaps with the MMA phase below)
        if (k0 + 32 < DD) {
            #pragma unroll
            for (int i = 0; i < 4; i++)
                aR[i] = *(const float4*)(A + (long)ar[i] * DD + k0 + 32 + asg[i] * 4);
            #pragma unroll
            for (int i = 0; i < 2; i++)
                bR[i] = *(const float4*)(W + (long)(k0 + 32 + br[i]) * HD + bsg[i] * 4);
        }

        #pragma unroll
        for (int kk = 0; kk < 32; kk += 8) {
            uint32_t a[2][4], bf[4][2];
            #pragma unroll
            for (int s_ = 0; s_ < 2; s_++) {
                int row = wm * 32 + s_ * 16 + g;
                a[s_][0] = As[row * 36 + kk + t];
                a[s_][1] = As[(row + 8) * 36 + kk + t];
                a[s_][2] = As[row * 36 + kk + t + 4];
                a[s_][3] = As[(row + 8) * 36 + kk + t + 4];
            }
            #pragma unroll
            for (int nt = 0; nt < 4; nt++) {
                int col = wn * 32 + nt * 8 + g;
                bf[nt][0] = Bs[(kk + t) * 72 + col];
                bf[nt][1] = Bs[(kk + t + 4) * 72 + col];
            }
            #pragma unroll
            for (int s_ = 0; s_ < 2; s_++)
                #pragma unroll
                for (int nt = 0; nt < 4; nt++)
                    mma8(c[s_][nt], a[s_], bf[nt]);
        }
        __syncthreads();
    }

    #pragma unroll
    for (int s_ = 0; s_ < 2; s_++) {
        int row = s0 + wm * 32 + s_ * 16 + g;
        #pragma unroll
        for (int nt = 0; nt < 4; nt++) {
            int col = wn * 32 + nt * 8 + 2 * t;
            float b0 = bias[col], b1 = bias[col + 1];
            long base0 = ((long)bh * SS + row) * HD + col;
            long base1 = ((long)bh * SS + row + 8) * HD + col;
            outp[base0]     = c[s_][nt][0] + b0;
            outp[base0 + 1] = c[s_][nt][1] + b1;
            outp[base1]     = c[s_][nt][2] + b0;
            outp[base1 + 1] = c[s_][nt][3] + b1;
        }
    }
}

// ---------------------------------------------------------------------------
// Kernel 2: flash attention, software-pipelined K/V staging.
// grid = (S/128, B*H), block = 256 (8 warps x 16 q-rows).
// ---------------------------------------------------------------------------
#define ATTN_SMEM ((128*68 + 64*68 + 64*72 + 128*68) * 4)

__global__ void __launch_bounds__(256, 2) attn_kernel()
{
    extern __shared__ uint32_t sm[];
    uint32_t* Qs = sm;                       // [128][68]
    uint32_t* Ks = Qs + 128 * 68;            // [64][68]
    uint32_t* Vs = Ks + 64 * 68;             // [64][72]
    uint32_t* Ps = Vs + 64 * 72;             // [128][68]

    int tid = threadIdx.x;
    int wid = tid >> 5, lane = tid & 31;
    int g = lane >> 2, t = lane & 3;
    int m0 = wid * 16;
    int q0 = blockIdx.x * 128;
    int bh = blockIdx.y;

    const float* Qg = g_Q + ((long)bh * SS + q0) * HD;
    const float* Kg = g_K + (long)bh * SS * HD;
    const float* Vg = g_V + (long)bh * SS * HD;

    // Stage Q (covered by the first __syncthreads inside the loop)
    #pragma unroll
    for (int i = 0; i < 8; i++) {
        int idx = tid + i * 256;
        int r = idx >> 4, sg = idx & 15;
        *(uint4*)(Qs + r * 68 + sg * 4) =
            tf4(*(const float4*)(Qg + (long)r * HD + sg * 4));
    }

    int sr[4], ssg[4];
    #pragma unroll
    for (int i = 0; i < 4; i++) { int idx = tid + i*256; sr[i] = idx >> 4; ssg[i] = idx & 15; }

    // Prologue: prefetch K/V tile 0
    float4 kR[4], vR[4];
    #pragma unroll
    for (int i = 0; i < 4; i++) {
        kR[i] = *(const float4*)(Kg + (long)sr[i] * HD + ssg[i] * 4);
        vR[i] = *(const float4*)(Vg + (long)sr[i] * HD + ssg[i] * 4);
    }

    float o[8][4];
    #pragma unroll
    for (int nt = 0; nt < 8; nt++)
        #pragma unroll
        for (int j = 0; j < 4; j++) o[nt][j] = 0.f;
    float mrow0 = -1e30f, mrow1 = -1e30f;
    float lrow0 = 0.f, lrow1 = 0.f;
    const float inv_scale = 1.0f / (8.0f + 1e-6f);  // 1/(sqrt(64)+EPS)

    for (int kt = 0; kt < SS; kt += 64) {
        // Commit prefetched K/V to smem
        #pragma unroll
        for (int i = 0; i < 4; i++) {
            *(uint4*)(Ks + sr[i] * 68 + ssg[i] * 4) = tf4(kR[i]);
            *(uint4*)(Vs + sr[i] * 72 + ssg[i] * 4) = tf4(vR[i]);
        }
        __syncthreads();

        // Prefetch next K/V tile (overlaps with both MMA phases)
        if (kt + 64 < SS) {
            #pragma unroll
            for (int i = 0; i < 4; i++) {
                kR[i] = *(const float4*)(Kg + (long)(kt + 64 + sr[i]) * HD + ssg[i] * 4);
                vR[i] = *(const float4*)(Vg + (long)(kt + 64 + sr[i]) * HD + ssg[i] * 4);
            }
        }

        // Phase 1: S = Q @ K^T
        float s[8][4];
        #pragma unroll
        for (int nt = 0; nt < 8; nt++)
            #pragma unroll
            for (int j = 0; j < 4; j++) s[nt][j] = 0.f;

        #pragma unroll
        for (int kk = 0; kk < 64; kk += 8) {
            uint32_t a[4];
            a[0] = Qs[(m0 + g) * 68 + kk + t];
            a[1] = Qs[(m0 + g + 8) * 68 + kk + t];
            a[2] = Qs[(m0 + g) * 68 + kk + t + 4];
            a[3] = Qs[(m0 + g + 8) * 68 + kk + t + 4];
            #pragma unroll
            for (int nt = 0; nt < 8; nt++) {
                uint32_t bf[2];
                bf[0] = Ks[(nt * 8 + g) * 68 + kk + t];
                bf[1] = Ks[(nt * 8 + g) * 68 + kk + t + 4];
                mma8(s[nt], a, bf);
            }
        }

        // Online softmax
        #pragma unroll
        for (int nt = 0; nt < 8; nt++)
            #pragma unroll
            for (int j = 0; j < 4; j++) s[nt][j] *= inv_scale;

        float mx0 = -1e30f, mx1 = -1e30f;
        #pragma unroll
        for (int nt = 0; nt < 8; nt++) {
            mx0 = fmaxf(mx0, fmaxf(s[nt][0], s[nt][1]));
            mx1 = fmaxf(mx1, fmaxf(s[nt][2], s[nt][3]));
        }
        mx0 = fmaxf(mx0, __shfl_xor_sync(0xffffffffu, mx0, 1));
        mx0 = fmaxf(mx0, __shfl_xor_sync(0xffffffffu, mx0, 2));
        mx1 = fmaxf(mx1, __shfl_xor_sync(0xffffffffu, mx1, 1));
        mx1 = fmaxf(mx1, __shfl_xor_sync(0xffffffffu, mx1, 2));

        float mn0 = fmaxf(mrow0, mx0), mn1 = fmaxf(mrow1, mx1);
        float cr0 = __expf(mrow0 - mn0), cr1 = __expf(mrow1 - mn1);
        float rs0 = 0.f, rs1 = 0.f;
        #pragma unroll
        for (int nt = 0; nt < 8; nt++) {
            s[nt][0] = __expf(s[nt][0] - mn0);
            s[nt][1] = __expf(s[nt][1] - mn0);
            s[nt][2] = __expf(s[nt][2] - mn1);
            s[nt][3] = __expf(s[nt][3] - mn1);
            rs0 += s[nt][0] + s[nt][1];
            rs1 += s[nt][2] + s[nt][3];
        }
        rs0 += __shfl_xor_sync(0xffffffffu, rs0, 1);
        rs0 += __shfl_xor_sync(0xffffffffu, rs0, 2);
        rs1 += __shfl_xor_sync(0xffffffffu, rs1, 1);
        rs1 += __shfl_xor_sync(0xffffffffu, rs1, 2);
        lrow0 = lrow0 * cr0 + rs0;
        lrow1 = lrow1 * cr1 + rs1;
        mrow0 = mn0; mrow1 = mn1;

        #pragma unroll
        for (int nt = 0; nt < 8; nt++) {
            o[nt][0] *= cr0; o[nt][1] *= cr0;
            o[nt][2] *= cr1; o[nt][3] *= cr1;
            int col = nt * 8 + 2 * t;
            Ps[(m0 + g) * 68 + col]         = f2tf(s[nt][0]);
            Ps[(m0 + g) * 68 + col + 1]     = f2tf(s[nt][1]);
            Ps[(m0 + g + 8) * 68 + col]     = f2tf(s[nt][2]);
            Ps[(m0 + g + 8) * 68 + col + 1] = f2tf(s[nt][3]);
        }
        __syncwarp();  // P rows are warp-private

        // Phase 2: O += P @ V
        #pragma unroll
        for (int kk = 0; kk < 64; kk += 8) {
            uint32_t a[4];
            a[0] = Ps[(m0 + g) * 68 + kk + t];
            a[1] = Ps[(m0 + g + 8) * 68 + kk + t];
            a[2] = Ps[(m0 + g) * 68 + kk + t + 4];
            a[3] = Ps[(m0 + g + 8) * 68 + kk + t + 4];
            #pragma unroll
            for (int nt = 0; nt < 8; nt++) {
                uint32_t bf[2];
                bf[0] = Vs[(kk + t) * 72 + nt * 8 + g];
                bf[1] = Vs[(kk + t + 4) * 72 + nt * 8 + g];
                mma8(o[nt], a, bf);
            }
        }
        __syncthreads();  // protect Ks/Vs before next commit
    }

    int b = bh / HH, h = bh % HH;
    float il0 = 1.0f / lrow0, il1 = 1.0f / lrow1;
    long r0 = ((long)b * SS + q0 + m0 + g) * DD + h * HD;
    long r1 = ((long)b * SS + q0 + m0 + g + 8) * DD + h * HD;
    #pragma unroll
    for (int nt = 0; nt < 8; nt++) {
        int col = nt * 8 + 2 * t;
        g_ctx[r0 + col]     = o[nt][0] * il0;
        g_ctx[r0 + col + 1] = o[nt][1] * il0;
        g_ctx[r1 + col]     = o[nt][2] * il1;
        g_ctx[r1 + col + 1] = o[nt][3] * il1;
    }
}

// ---------------------------------------------------------------------------
// Kernel 3: output projection, software-pipelined.
// grid = (B*S/128, D/64), block = 256.
// ---------------------------------------------------------------------------
__global__ void __launch_bounds__(256) proj_kernel(
    const float* __restrict__ Wp, const float* __restrict__ bp,
    float* __restrict__ out)
{
    __shared__ uint32_t As[128 * 36];
    __shared__ uint32_t Bs[32 * 72];

    int tid = threadIdx.x;
    int wid = tid >> 5, lane = tid & 31;
    int g = lane >> 2, t = lane & 3;
    int wm = wid & 3, wn = wid >> 2;
    int m0 = blockIdx.x * 128;
    int n0 = blockIdx.y * 64;

    const float* A = g_ctx + (long)m0 * DD;

    int ar[4], asg[4], br[2], bsg[2];
    #pragma unroll
    for (int i = 0; i < 4; i++) { int idx = tid + i*256; ar[i] = idx >> 3; asg[i] = idx & 7; }
    #pragma unroll
    for (int i = 0; i < 2; i++) { int idx = tid + i*256; br[i] = idx >> 4; bsg[i] = idx & 15; }

    float c[2][4][4];
    #pragma unroll
    for (int s_ = 0; s_ < 2; s_++)
        #pragma unroll
        for (int nt = 0; nt < 4; nt++)
            #pragma unroll
            for (int j = 0; j < 4; j++) c[s_][nt][j] = 0.f;

    float4 aR[4], bR[2];
    #pragma unroll
    for (int i = 0; i < 4; i++)
        aR[i] = *(const float4*)(A + (long)ar[i] * DD + asg[i] * 4);
    #pragma unroll
    for (int i = 0; i < 2; i++)
        bR[i] = *(const float4*)(Wp + (long)br[i] * DD + n0 + bsg[i] * 4);

    for (int k0 = 0; k0 < DD; k0 += 32) {
        #pragma unroll
        for (int i = 0; i < 4; i++)
            *(uint4*)(As + ar[i] * 36 + asg[i] * 4) = tf4(aR[i]);
        #pragma unroll
        for (int i = 0; i < 2; i++)
            *(uint4*)(Bs + br[i] * 72 + bsg[i] * 4) = tf4(bR[i]);
        __syncthreads();

        if (k0 + 32 < DD) {
            #pragma unroll
            for (int i = 0; i < 4; i++)
                aR[i] = *(const float4*)(A + (long)ar[i] * DD + k0 + 32 + asg[i] * 4);
            #pragma unroll
            for (int i = 0; i < 2; i++)
                bR[i] = *(const float4*)(Wp + (long)(k0 + 32 + br[i]) * DD + n0 + bsg[i] * 4);
        }

        #pragma unroll
        for (int kk = 0; kk < 32; kk += 8) {
            uint32_t a[2][4], bf[4][2];
            #pragma unroll
            for (int s_ = 0; s_ < 2; s_++) {
                int row = wm * 32 + s_ * 16 + g;
                a[s_][0] = As[row * 36 + kk + t];
                a[s_][1] = As[(row + 8) * 36 + kk + t];
                a[s_][2] = As[row * 36 + kk + t + 4];
                a[s_][3] = As[(row + 8) * 36 + kk + t + 4];
            }
            #pragma unroll
            for (int nt = 0; nt < 4; nt++) {
                int col = wn * 32 + nt * 8 + g;
                bf[nt][0] = Bs[(kk + t) * 72 + col];
                bf[nt][1] = Bs[(kk + t + 4) * 72 + col];
            }
            #pragma unroll
            for (int s_ = 0; s_ < 2; s_++)
                #pragma unroll
                for (int nt = 0; nt < 4; nt++)
                    mma8(c[s_][nt], a[s_], bf[nt]);
        }
        __syncthreads();
    }

    #pragma unroll
    for (int s_ = 0; s_ < 2; s_++) {
        int row = m0 + wm * 32 + s_ * 16 + g;
        #pragma unroll
        for (int nt = 0; nt < 4; nt++) {
            int col = n0 + wn * 32 + nt * 8 + 2 * t;
            float b0 = bp[col], b1 = bp[col + 1];
            out[(long)row * DD + col]           = c[s_][nt][0] + b0;
            out[(long)row * DD + col + 1]       = c[s_][nt][1] + b1;
            out[(long)(row + 8) * DD + col]     = c[s_][nt][2] + b0;
            out[(long)(row + 8) * DD + col + 1] = c[s_][nt][3] + b1;
        }
    }
}

// ---------------------------------------------------------------------------
extern "C" void kernel_launch(void* const* d_in, const int* in_sizes, int n_in,
                              void* d_out, int out_size)
{
    const float* x  = (const float*)d_in[0];
    const float* Wq = (const float*)d_in[1];
    const float* bq = (const float*)d_in[2];
    const float* Wk = (const float*)d_in[3];
    const float* bk = (const float*)d_in[4];
    const float* Wv = (const float*)d_in[5];
    const float* bv = (const float*)d_in[6];
    const float* Wp = (const float*)d_in[7];
    const float* bp = (const float*)d_in[8];
    float* out = (float*)d_out;

    cudaFuncSetAttribute(attn_kernel, cudaFuncAttributeMaxDynamicSharedMemorySize,
                         ATTN_SMEM);

    qkv_kernel<<<dim3(SS / 128, BB * HH, 3), 256>>>(x, Wq, bq, Wk, bk, Wv, bv);
    attn_kernel<<<dim3(SS / 128, BB * HH), 256, ATTN_SMEM>>>();
    proj_kernel<<<dim3((BB * SS) / 128, DD / 64), 256>>>(Wp, bp, out);
}